// round 16
// baseline (speedup 1.0000x reference)
#include <cuda_runtime.h>
#include <cuda_bf16.h>
#include <math.h>
#include <stdint.h>

// Problem constants (fixed shapes from setup_inputs)
#define TOK   8192      // B*N = 4*2048 tokens
#define CDIM  512
#define DFF   2048
#define NHEAD 8
#define HDIM  64
#define SEQ   2048

// ------------------- scratch (device globals; no allocation) -------------------
__device__ float g_qkv [TOK * 3 * CDIM];
__device__ float g_s   [TOK * CDIM];
__device__ float g_gate[TOK * CDIM];
__device__ float g_x1  [TOK * CDIM];
// bf16 split activations: [M, 3K] layout = [hi | lo | hi]
__device__ __nv_bfloat16 b_xn  [TOK * 3 * CDIM];
__device__ __nv_bfloat16 b_en  [TOK * 3 * CDIM];
__device__ __nv_bfloat16 b_att [TOK * 3 * CDIM];
__device__ __nv_bfloat16 b_xn3 [TOK * 3 * CDIM];
__device__ __nv_bfloat16 b_h   [TOK * 3 * DFF];
// bf16 split weights: [N, 3K] layout = [Bh | Bh | Bl]  (K-major rows)
__device__ __nv_bfloat16 b_wqkv [3 * CDIM * 3 * CDIM];
__device__ __nv_bfloat16 b_ws   [CDIM * 3 * CDIM];
__device__ __nv_bfloat16 b_wgate[CDIM * 3 * CDIM];
__device__ __nv_bfloat16 b_wproj[CDIM * 3 * CDIM];
__device__ __nv_bfloat16 b_wfc1 [DFF * 3 * CDIM];
__device__ __nv_bfloat16 b_wfc2 [CDIM * 3 * DFF];

// ------------------- helpers -------------------
__device__ __forceinline__ uint32_t smem_u32(const void* p) {
    uint32_t a;
    asm("{ .reg .u64 t; cvta.to.shared.u64 t, %1; cvt.u32.u64 %0, t; }" : "=r"(a) : "l"(p));
    return a;
}
__device__ __forceinline__ void cp_async16(uint32_t dst, const void* src) {
    asm volatile("cp.async.cg.shared.global [%0], [%1], 16;" :: "r"(dst), "l"(src) : "memory");
}
__device__ __forceinline__ void cp_commit() {
    asm volatile("cp.async.commit_group;" ::: "memory");
}
template <int N>
__device__ __forceinline__ void cp_wait() {
    asm volatile("cp.async.wait_group %0;" :: "n"(N) : "memory");
}
__device__ __forceinline__ void mma16816(float* c, const uint32_t* a, const uint32_t* b) {
    asm volatile(
        "mma.sync.aligned.m16n8k16.row.col.f32.bf16.bf16.f32 "
        "{%0,%1,%2,%3}, {%4,%5,%6,%7}, {%8,%9}, {%0,%1,%2,%3};"
        : "+f"(c[0]), "+f"(c[1]), "+f"(c[2]), "+f"(c[3])
        : "r"(a[0]), "r"(a[1]), "r"(a[2]), "r"(a[3]), "r"(b[0]), "r"(b[1]));
}
__device__ __forceinline__ void ldsm_x4(uint32_t* r, uint32_t addr) {
    asm volatile("ldmatrix.sync.aligned.m8n8.x4.shared.b16 {%0,%1,%2,%3}, [%4];"
                 : "=r"(r[0]), "=r"(r[1]), "=r"(r[2]), "=r"(r[3]) : "r"(addr));
}

static __device__ __forceinline__ void store_split4(__nv_bfloat16* dst, size_t base, int seglen,
                                                    float a, float b, float c, float d) {
    __nv_bfloat16 h0 = __float2bfloat16(a), h1 = __float2bfloat16(b);
    __nv_bfloat16 h2 = __float2bfloat16(c), h3 = __float2bfloat16(d);
    *(__nv_bfloat162*)&dst[base]     = __halves2bfloat162(h0, h1);
    *(__nv_bfloat162*)&dst[base + 2] = __halves2bfloat162(h2, h3);
    *(__nv_bfloat162*)&dst[base + 2 * (size_t)seglen]     = __halves2bfloat162(h0, h1);
    *(__nv_bfloat162*)&dst[base + 2 * (size_t)seglen + 2] = __halves2bfloat162(h2, h3);
    float l0 = a - __bfloat162float(h0), l1 = b - __bfloat162float(h1);
    float l2 = c - __bfloat162float(h2), l3 = d - __bfloat162float(h3);
    *(__nv_bfloat162*)&dst[base + (size_t)seglen] =
        __halves2bfloat162(__float2bfloat16(l0), __float2bfloat16(l1));
    *(__nv_bfloat162*)&dst[base + (size_t)seglen + 2] =
        __halves2bfloat162(__float2bfloat16(l2), __float2bfloat16(l3));
}

static __device__ __forceinline__ void store_split2(__nv_bfloat16* dst, size_t base, int seglen,
                                                    float a, float b) {
    __nv_bfloat16 h0 = __float2bfloat16(a), h1 = __float2bfloat16(b);
    __nv_bfloat162 hp = __halves2bfloat162(h0, h1);
    *(__nv_bfloat162*)&dst[base] = hp;
    *(__nv_bfloat162*)&dst[base + 2 * (size_t)seglen] = hp;
    float l0 = a - __bfloat162float(h0), l1 = b - __bfloat162float(h1);
    *(__nv_bfloat162*)&dst[base + (size_t)seglen] =
        __halves2bfloat162(__float2bfloat16(l0), __float2bfloat16(l1));
}

static __device__ __forceinline__ void split_hl(float v, __nv_bfloat16& h, __nv_bfloat16& l) {
    h = __float2bfloat16(v);
    l = __float2bfloat16(v - __bfloat162float(h));
}

// ------------------- fused weight split: all 6 weights in one launch -------------------
__global__ void wsplit_all(
    const float* __restrict__ w0, const float* __restrict__ w1, const float* __restrict__ w2,
    const float* __restrict__ w3, const float* __restrict__ w4, const float* __restrict__ w5,
    __nv_bfloat16* __restrict__ o0, __nv_bfloat16* __restrict__ o1, __nv_bfloat16* __restrict__ o2,
    __nv_bfloat16* __restrict__ o3, __nv_bfloat16* __restrict__ o4, __nv_bfloat16* __restrict__ o5)
{
    int bid = blockIdx.x;
    const float* W; __nv_bfloat16* Wb; int K, N, t;
    if      (bid < 768)  { W = w0; Wb = o0; K = 512;  N = 1536; t = bid; }
    else if (bid < 1024) { W = w1; Wb = o1; K = 512;  N = 512;  t = bid - 768; }
    else if (bid < 1280) { W = w2; Wb = o2; K = 512;  N = 512;  t = bid - 1024; }
    else if (bid < 1536) { W = w3; Wb = o3; K = 512;  N = 512;  t = bid - 1280; }
    else if (bid < 2560) { W = w4; Wb = o4; K = 512;  N = 2048; t = bid - 1536; }
    else                 { W = w5; Wb = o5; K = 2048; N = 512;  t = bid - 2560; }
    int nx = N >> 5;
    int n0 = (t % nx) * 32, k0 = (t / nx) * 32;

    __shared__ float tile[32][33];
    int tx = threadIdx.x, ty = threadIdx.y;  // 32 x 8
    for (int i = ty; i < 32; i += 8) tile[i][tx] = W[(size_t)(k0 + i) * N + n0 + tx];
    __syncthreads();
    for (int i = ty; i < 32; i += 8) {
        int n = n0 + i, k = k0 + tx;
        float v = tile[tx][i];
        __nv_bfloat16 h = __float2bfloat16(v);
        float lo = v - __bfloat162float(h);
        size_t base = (size_t)n * 3 * K + k;
        Wb[base]         = h;
        Wb[base + K]     = h;
        Wb[base + 2 * K] = __float2bfloat16(lo);
    }
}

// ------------------- LayerNorm -> bf16 split triple -------------------
__global__ void ln2_split(const float* __restrict__ xa, const float* __restrict__ wa,
                          const float* __restrict__ ba, __nv_bfloat16* __restrict__ ya,
                          const float* __restrict__ xb, const float* __restrict__ wb,
                          const float* __restrict__ bb, __nv_bfloat16* __restrict__ yb)
{
    int row = blockIdx.x;
    const float *x = xa, *w = wa, *b = ba;
    __nv_bfloat16* y = ya;
    if (row >= TOK) { row -= TOK; x = xb; w = wb; b = bb; y = yb; }

    int tid = threadIdx.x;
    float4 v = ((const float4*)(x + (size_t)row * CDIM))[tid];
    float s  = v.x + v.y + v.z + v.w;
    float ss = v.x * v.x + v.y * v.y + v.z * v.z + v.w * v.w;
#pragma unroll
    for (int off = 16; off > 0; off >>= 1) {
        s  += __shfl_xor_sync(0xffffffffu, s,  off);
        ss += __shfl_xor_sync(0xffffffffu, ss, off);
    }
    __shared__ float rs[4], rss[4];
    int wid = tid >> 5;
    if ((tid & 31) == 0) { rs[wid] = s; rss[wid] = ss; }
    __syncthreads();
    s  = rs[0] + rs[1] + rs[2] + rs[3];
    ss = rss[0] + rss[1] + rss[2] + rss[3];
    float mean = s * (1.0f / CDIM);
    float var  = ss * (1.0f / CDIM) - mean * mean;
    float rstd = rsqrtf(var + 1e-5f);
    float4 w4 = ((const float4*)w)[tid];
    float4 b4 = ((const float4*)b)[tid];
    float o0 = (v.x - mean) * rstd * w4.x + b4.x;
    float o1 = (v.y - mean) * rstd * w4.y + b4.y;
    float o2 = (v.z - mean) * rstd * w4.z + b4.z;
    float o3 = (v.w - mean) * rstd * w4.w + b4.w;
    store_split4(y, (size_t)row * 3 * CDIM + tid * 4, CDIM, o0, o1, o2, o3);
}

__global__ void ln_split(const float* __restrict__ x, const float* __restrict__ w,
                         const float* __restrict__ b, __nv_bfloat16* __restrict__ y)
{
    int row = blockIdx.x;
    int tid = threadIdx.x;
    float4 v = ((const float4*)(x + (size_t)row * CDIM))[tid];
    float s  = v.x + v.y + v.z + v.w;
    float ss = v.x * v.x + v.y * v.y + v.z * v.z + v.w * v.w;
#pragma unroll
    for (int off = 16; off > 0; off >>= 1) {
        s  += __shfl_xor_sync(0xffffffffu, s,  off);
        ss += __shfl_xor_sync(0xffffffffu, ss, off);
    }
    __shared__ float rs[4], rss[4];
    int wid = tid >> 5;
    if ((tid & 31) == 0) { rs[wid] = s; rss[wid] = ss; }
    __syncthreads();
    s  = rs[0] + rs[1] + rs[2] + rs[3];
    ss = rss[0] + rss[1] + rss[2] + rss[3];
    float mean = s * (1.0f / CDIM);
    float var  = ss * (1.0f / CDIM) - mean * mean;
    float rstd = rsqrtf(var + 1e-5f);
    float4 w4 = ((const float4*)w)[tid];
    float4 b4 = ((const float4*)b)[tid];
    float o0 = (v.x - mean) * rstd * w4.x + b4.x;
    float o1 = (v.y - mean) * rstd * w4.y + b4.y;
    float o2 = (v.z - mean) * rstd * w4.z + b4.z;
    float o3 = (v.w - mean) * rstd * w4.w + b4.w;
    store_split4(y, (size_t)row * 3 * CDIM + tid * 4, CDIM, o0, o1, o2, o3);
}

// ------------------- HMMA GEMM: C[M,N] = A'[M,K3] @ B'[N,K3]^T -------------------
// 3-stage cp.async pipeline, one barrier per stage.
__device__ __forceinline__ float gelu_erf(float v) {
    return 0.5f * v * (1.0f + erff(v * 0.70710678118654752f));
}

#define GPITCH_B 144                      // bytes per smem row (72 bf16)
#define GTILE_B  (128 * GPITCH_B)        // 18432 B per tile
#define GSTAGE_B (2 * GTILE_B)           // A+B per stage = 36864 B
#define GEMM_SMEM (3 * GSTAGE_B)         // 3 stages = 110592 B

template <int MODE>
__global__ void __launch_bounds__(256, 2) gemm_mma(
    const __nv_bfloat16* __restrict__ A, const __nv_bfloat16* __restrict__ B,
    const float* __restrict__ bias, const float* __restrict__ res,
    void* __restrict__ Cout, int M, int N, int K3)
{
    extern __shared__ char sm[];
    const uint32_t smb = smem_u32(sm);
    const int tid  = threadIdx.x;
    const int lane = tid & 31;
    const int wid  = tid >> 5;
    const int wm   = wid >> 2;        // 0..1 : 64-row half
    const int wn   = wid & 3;         // 0..3 : 32-col quarter
    const int lr   = lane >> 2;       // 0..7
    const int lk2  = (lane & 3) * 2;  // 0,2,4,6

    const int m0 = blockIdx.y * 128, n0 = blockIdx.x * 128;
    const int NT = K3 >> 6;

    const int ldrow = tid >> 3;
    const int ldkc  = tid & 7;

    // ldmatrix per-lane address components
    const int a_row  = wm * 64 + (lane & 15);        // + mt*16
    const int a_boff = (lane >> 4) * 16;
    const int b_row  = wn * 32 + ((lane >> 4) & 1) * 8 + (lane & 7);  // + p*16
    const int b_boff = ((lane >> 3) & 1) * 16;

    float acc[4][4][4];
#pragma unroll
    for (int a = 0; a < 4; a++)
#pragma unroll
        for (int b = 0; b < 4; b++)
#pragma unroll
            for (int c = 0; c < 4; c++) acc[a][b][c] = 0.0f;

    auto issue = [&](int kt, int bsel) {
        uint32_t sa = smb + bsel * GSTAGE_B;
        uint32_t sb = sa + GTILE_B;
#pragma unroll
        for (int t = 0; t < 4; t++) {
            int row = ldrow + t * 32;
            uint32_t off = (uint32_t)(row * GPITCH_B + ldkc * 16);
            cp_async16(sa + off, A + (size_t)(m0 + row) * K3 + kt * 64 + ldkc * 8);
            cp_async16(sb + off, B + (size_t)(n0 + row) * K3 + kt * 64 + ldkc * 8);
        }
        cp_commit();
    };

    issue(0, 0);
    issue(1, 1);

    int bsel = 0, bnext = 2;   // buffer of stage kt; buffer for stage kt+2
    for (int kt = 0; kt < NT; kt++) {
        // stage kt arrives: pending groups at loop top = {kt, kt+1}
        if (kt + 1 < NT) cp_wait<1>();
        else             cp_wait<0>();
        __syncthreads();                 // all warps done reading buf of stage kt-1
        if (kt + 2 < NT) issue(kt + 2, bnext);

        const uint32_t bufA = smb + bsel * GSTAGE_B;
        const uint32_t bufB = bufA + GTILE_B;

#pragma unroll
        for (int s = 0; s < 4; s++) {
            uint32_t af[4][4];
#pragma unroll
            for (int mt = 0; mt < 4; mt++)
                ldsm_x4(af[mt], bufA + (a_row + mt * 16) * GPITCH_B + s * 32 + a_boff);
            uint32_t bfr[8];
#pragma unroll
            for (int p = 0; p < 2; p++)
                ldsm_x4(&bfr[p * 4], bufB + (b_row + p * 16) * GPITCH_B + s * 32 + b_boff);
#pragma unroll
            for (int mt = 0; mt < 4; mt++)
#pragma unroll
                for (int nt = 0; nt < 4; nt++)
                    mma16816(acc[mt][nt], af[mt], &bfr[nt * 2]);
        }
        bsel  = (bsel  == 2) ? 0 : bsel + 1;
        bnext = (bnext == 2) ? 0 : bnext + 1;
    }

#pragma unroll
    for (int mt = 0; mt < 4; mt++) {
#pragma unroll
        for (int half = 0; half < 2; half++) {
            const int row = m0 + wm * 64 + mt * 16 + lr + half * 8;
#pragma unroll
            for (int nt = 0; nt < 4; nt++) {
                const int col = n0 + wn * 32 + nt * 8 + lk2;
                float v0 = acc[mt][nt][half * 2 + 0];
                float v1 = acc[mt][nt][half * 2 + 1];
                if (MODE & 1) {
                    float2 bb = *(const float2*)&bias[col];
                    v0 += bb.x; v1 += bb.y;
                }
                if (MODE & 2) { v0 = gelu_erf(v0); v1 = gelu_erf(v1); }
                if (MODE & 4) {
                    float2 rr = *(const float2*)&res[(size_t)row * N + col];
                    v0 += rr.x; v1 += rr.y;
                }
                if (MODE & 8) {
                    store_split2((__nv_bfloat16*)Cout, (size_t)row * 3 * N + col, N, v0, v1);
                } else {
                    float2 o = make_float2(v0, v1);
                    *(float2*)&((float*)Cout)[(size_t)row * N + col] = o;
                }
            }
        }
    }
}

// ------------------- Flash attention via HMMA, split-3 on QK^T and PV -------------------
#define APITCH 136
#define APITCH_B (APITCH * 2)
#define ATT_SMEM ((128 + 64 + 64 + 128) * APITCH * 2)   // 104448 B

__global__ void __launch_bounds__(256, 2) attn_mma(
    const float* __restrict__ qkv, const float* __restrict__ sbuf,
    const float* __restrict__ gate, __nv_bfloat16* __restrict__ out)
{
    extern __shared__ char smc[];
    __nv_bfloat16* qs = (__nv_bfloat16*)smc;        // [128][APITCH]  q*scale split
    __nv_bfloat16* ks = qs + 128 * APITCH;          // [64][APITCH]   (k+s) split
    __nv_bfloat16* vs = ks + 64 * APITCH;           // [64][APITCH]   V^T split
    __nv_bfloat16* ps = vs + 64 * APITCH;           // [128][APITCH]  P split

    const uint32_t qs_u = smem_u32(qs);
    const uint32_t ks_u = smem_u32(ks);
    const uint32_t vs_u = smem_u32(vs);
    const uint32_t ps_u = smem_u32(ps);

    const int tid  = threadIdx.x;
    const int lane = tid & 31;
    const int wid  = tid >> 5;          // 0..7
    const int wr0  = wid * 16;          // warp's 16-row band
    const int lr   = lane >> 2;         // 0..7
    const int lc2  = (lane & 3) * 2;    // 0,2,4,6

    const int a_row  = wr0 + (lane & 15);
    const int a_boff = (lane >> 4) * 16;
    const int b_row  = ((lane >> 4) & 1) * 8 + (lane & 7);   // + p*16
    const int b_boff = ((lane >> 3) & 1) * 16;

    const int bh = blockIdx.y;
    const int b  = bh >> 3, h = bh & 7;
    const int q0 = blockIdx.x * 128;
    const int mbase = b * SEQ;
    const int qoff = h * HDIM;
    const int koff = CDIM + h * HDIM;
    const int voff = 2 * CDIM + h * HDIM;
    const int soff = h * HDIM;
    const float scale = 0.125f;

    for (int i = tid; i < 128 * 16; i += 256) {
        int r  = i >> 4;
        int d4 = (i & 15) * 4;
        float4 v = *(const float4*)&qkv[(size_t)(mbase + q0 + r) * (3 * CDIM) + qoff + d4];
        v.x *= scale; v.y *= scale; v.z *= scale; v.w *= scale;
        __nv_bfloat16 h0, l0, h1, l1, h2, l2, h3, l3;
        split_hl(v.x, h0, l0); split_hl(v.y, h1, l1);
        split_hl(v.z, h2, l2); split_hl(v.w, h3, l3);
        __nv_bfloat16* row = qs + r * APITCH;
        *(__nv_bfloat162*)&row[d4]          = __halves2bfloat162(h0, h1);
        *(__nv_bfloat162*)&row[d4 + 2]      = __halves2bfloat162(h2, h3);
        *(__nv_bfloat162*)&row[64 + d4]     = __halves2bfloat162(l0, l1);
        *(__nv_bfloat162*)&row[64 + d4 + 2] = __halves2bfloat162(l2, l3);
    }

    float m_i[2] = {-1e30f, -1e30f};
    float l_i[2] = {0.0f, 0.0f};
    float oacc[8][4];
#pragma unroll
    for (int d = 0; d < 8; d++)
#pragma unroll
        for (int j = 0; j < 4; j++) oacc[d][j] = 0.0f;

    for (int kt = 0; kt < SEQ; kt += 64) {
        __syncthreads();
        for (int i = tid; i < 64 * 16; i += 256) {
            int c  = i >> 4;
            int d4 = (i & 15) * 4;
            size_t row = (size_t)(mbase + kt + c);
            float4 kv = *(const float4*)&qkv[row * (3 * CDIM) + koff + d4];
            float4 sv = *(const float4*)&sbuf[row * CDIM + soff + d4];
            kv.x += sv.x; kv.y += sv.y; kv.z += sv.z; kv.w += sv.w;
            __nv_bfloat16 h0, l0, h1, l1, h2, l2, h3, l3;
            split_hl(kv.x, h0, l0); split_hl(kv.y, h1, l1);
            split_hl(kv.z, h2, l2); split_hl(kv.w, h3, l3);
            __nv_bfloat16* krow = ks + c * APITCH;
            *(__nv_bfloat162*)&krow[d4]          = __halves2bfloat162(h0, h1);
            *(__nv_bfloat162*)&krow[d4 + 2]      = __halves2bfloat162(h2, h3);
            *(__nv_bfloat162*)&krow[64 + d4]     = __halves2bfloat162(l0, l1);
            *(__nv_bfloat162*)&krow[64 + d4 + 2] = __halves2bfloat162(l2, l3);
        }
        for (int i = tid; i < 64 * 32; i += 256) {
            int d  = i & 63;
            int c2 = (i >> 6) << 1;
            float f0 = qkv[(size_t)(mbase + kt + c2)     * (3 * CDIM) + voff + d];
            float f1 = qkv[(size_t)(mbase + kt + c2 + 1) * (3 * CDIM) + voff + d];
            __nv_bfloat16 h0, l0, h1, l1;
            split_hl(f0, h0, l0); split_hl(f1, h1, l1);
            __nv_bfloat16* vrow = vs + d * APITCH;
            *(__nv_bfloat162*)&vrow[c2]      = __halves2bfloat162(h0, h1);
            *(__nv_bfloat162*)&vrow[64 + c2] = __halves2bfloat162(l0, l1);
        }
        __syncthreads();

        float sacc[8][4];
#pragma unroll
        for (int nt = 0; nt < 8; nt++)
#pragma unroll
            for (int j = 0; j < 4; j++) sacc[nt][j] = 0.0f;

#pragma unroll
        for (int s12 = 0; s12 < 12; s12++) {
            const int seg = s12 >> 2, ch = s12 & 3;
            const int qc = (seg == 1) ? 4 + ch : ch;   // seg1 -> lo
            const int kc = (seg == 2) ? 4 + ch : ch;   // seg2 -> lo
            uint32_t af[4];
            ldsm_x4(af, qs_u + a_row * APITCH_B + qc * 32 + a_boff);
            uint32_t bfr[16];
#pragma unroll
            for (int p = 0; p < 4; p++)
                ldsm_x4(&bfr[p * 4], ks_u + (b_row + p * 16) * APITCH_B + kc * 32 + b_boff);
#pragma unroll
            for (int nt = 0; nt < 8; nt++)
                mma16816(sacc[nt], af, &bfr[nt * 2]);
        }

        float mx0 = -1e30f, mx1 = -1e30f;
#pragma unroll
        for (int nt = 0; nt < 8; nt++) {
            mx0 = fmaxf(mx0, fmaxf(sacc[nt][0], sacc[nt][1]));
            mx1 = fmaxf(mx1, fmaxf(sacc[nt][2], sacc[nt][3]));
        }
        mx0 = fmaxf(mx0, __shfl_xor_sync(0xffffffffu, mx0, 1));
        mx0 = fmaxf(mx0, __shfl_xor_sync(0xffffffffu, mx0, 2));
        mx1 = fmaxf(mx1, __shfl_xor_sync(0xffffffffu, mx1, 1));
        mx1 = fmaxf(mx1, __shfl_xor_sync(0xffffffffu, mx1, 2));
        const float mn0 = fmaxf(m_i[0], mx0);
        const float mn1 = fmaxf(m_i[1], mx1);
        const float corr0 = __expf(m_i[0] - mn0);
        const float corr1 = __expf(m_i[1] - mn1);
        float s0 = 0.0f, s1 = 0.0f;
#pragma unroll
        for (int nt = 0; nt < 8; nt++) {
            float p00 = __expf(sacc[nt][0] - mn0);
            float p01 = __expf(sacc[nt][1] - mn0);
            float p10 = __expf(sacc[nt][2] - mn1);
            float p11 = __expf(sacc[nt][3] - mn1);
            s0 += p00 + p01; s1 += p10 + p11;
            const int col = nt * 8 + lc2;
            __nv_bfloat16 h0, l0, h1, l1;
            split_hl(p00, h0, l0); split_hl(p01, h1, l1);
            __nv_bfloat16* r0 = ps + (wr0 + lr) * APITCH;
            *(__nv_bfloat162*)&r0[col]      = __halves2bfloat162(h0, h1);
            *(__nv_bfloat162*)&r0[64 + col] = __halves2bfloat162(l0, l1);
            split_hl(p10, h0, l0); split_hl(p11, h1, l1);
            __nv_bfloat16* r1 = ps + (wr0 + lr + 8) * APITCH;
            *(__nv_bfloat162*)&r1[col]      = __halves2bfloat162(h0, h1);
            *(__nv_bfloat162*)&r1[64 + col] = __halves2bfloat162(l0, l1);
        }
        s0 += __shfl_xor_sync(0xffffffffu, s0, 1);
        s0 += __shfl_xor_sync(0xffffffffu, s0, 2);
        s1 += __shfl_xor_sync(0xffffffffu, s1, 1);
        s1 += __shfl_xor_sync(0xffffffffu, s1, 2);
        l_i[0] = l_i[0] * corr0 + s0;
        l_i[1] = l_i[1] * corr1 + s1;
        m_i[0] = mn0; m_i[1] = mn1;
#pragma unroll
        for (int d = 0; d < 8; d++) {
            oacc[d][0] *= corr0; oacc[d][1] *= corr0;
            oacc[d][2] *= corr1; oacc[d][3] *= corr1;
        }
        __syncwarp();

#pragma unroll
        for (int s12 = 0; s12 < 12; s12++) {
            const int seg = s12 >> 2, ch = s12 & 3;
            const int pc = (seg == 1) ? 4 + ch : ch;
            const int vc = (seg == 2) ? 4 + ch : ch;
            uint32_t af[4];
            ldsm_x4(af, ps_u + a_row * APITCH_B + pc * 32 + a_boff);
            uint32_t bfr[16];
#pragma unroll
            for (int p = 0; p < 4; p++)
                ldsm_x4(&bfr[p * 4], vs_u + (b_row + p * 16) * APITCH_B + vc * 32 + b_boff);
#pragma unroll
            for (int dt = 0; dt < 8; dt++)
                mma16816(oacc[dt], af, &bfr[dt * 2]);
        }
    }

    const float inv0 = 1.0f / l_i[0];
    const float inv1 = 1.0f / l_i[1];
    const int r0 = mbase + q0 + wr0 + lr;
    const int r1 = r0 + 8;
#pragma unroll
    for (int dt = 0; dt < 8; dt++) {
        const int col = h * HDIM + dt * 8 + lc2;
        float2 g0 = *(const float2*)&gate[(size_t)r0 * CDIM + col];
        float2 g1 = *(const float2*)&gate[(size_t)r1 * CDIM + col];
        store_split2(out, (size_t)r0 * 3 * CDIM + col, CDIM,
                     oacc[dt][0] * inv0 * g0.x, oacc[dt][1] * inv0 * g0.y);
        store_split2(out, (size_t)r1 * 3 * CDIM + col, CDIM,
                     oacc[dt][2] * inv1 * g1.x, oacc[dt][3] * inv1 * g1.y);
    }
}

// ------------------- orchestration -------------------
extern "C" void kernel_launch(void* const* d_in, const int* in_sizes, int n_in,
                              void* d_out, int out_size)
{
    const float* x      = (const float*)d_in[0];
    const float* e      = (const float*)d_in[1];
    const float* w_qkv  = (const float*)d_in[2];
    const float* w_s    = (const float*)d_in[3];
    const float* w_gate = (const float*)d_in[4];
    const float* w_proj = (const float*)d_in[5];
    const float* b_proj = (const float*)d_in[6];
    const float* ln1_w  = (const float*)d_in[7];
    const float* ln1_b  = (const float*)d_in[8];
    const float* ln2_w  = (const float*)d_in[9];
    const float* ln2_b  = (const float*)d_in[10];
    const float* ln3_w  = (const float*)d_in[11];
    const float* ln3_b  = (const float*)d_in[12];
    const float* w_fc1  = (const float*)d_in[13];
    const float* b_fc1  = (const float*)d_in[14];
    const float* w_fc2  = (const float*)d_in[15];
    const float* b_fc2  = (const float*)d_in[16];
    float* out = (float*)d_out;

    float *p_qkv, *p_s, *p_gate, *p_x1;
    __nv_bfloat16 *p_xn, *p_en, *p_att, *p_xn3, *p_h;
    __nv_bfloat16 *p_wqkv, *p_ws, *p_wgate, *p_wproj, *p_wfc1, *p_wfc2;
    cudaGetSymbolAddress((void**)&p_qkv,  g_qkv);
    cudaGetSymbolAddress((void**)&p_s,    g_s);
    cudaGetSymbolAddress((void**)&p_gate, g_gate);
    cudaGetSymbolAddress((void**)&p_x1,   g_x1);
    cudaGetSymbolAddress((void**)&p_xn,   b_xn);
    cudaGetSymbolAddress((void**)&p_en,   b_en);
    cudaGetSymbolAddress((void**)&p_att,  b_att);
    cudaGetSymbolAddress((void**)&p_xn3,  b_xn3);
    cudaGetSymbolAddress((void**)&p_h,    b_h);
    cudaGetSymbolAddress((void**)&p_wqkv, b_wqkv);
    cudaGetSymbolAddress((void**)&p_ws,   b_ws);
    cudaGetSymbolAddress((void**)&p_wgate, b_wgate);
    cudaGetSymbolAddress((void**)&p_wproj, b_wproj);
    cudaGetSymbolAddress((void**)&p_wfc1, b_wfc1);
    cudaGetSymbolAddress((void**)&p_wfc2, b_wfc2);

    cudaFuncSetAttribute(attn_mma, cudaFuncAttributeMaxDynamicSharedMemorySize, ATT_SMEM);
    cudaFuncSetAttribute(gemm_mma<0>,  cudaFuncAttributeMaxDynamicSharedMemorySize, GEMM_SMEM);
    cudaFuncSetAttribute(gemm_mma<5>,  cudaFuncAttributeMaxDynamicSharedMemorySize, GEMM_SMEM);
    cudaFuncSetAttribute(gemm_mma<11>, cudaFuncAttributeMaxDynamicSharedMemorySize, GEMM_SMEM);

    // 0) split all weights -> bf16 [N,3K] (one launch)
    wsplit_all<<<3584, dim3(32, 8)>>>(w_qkv, w_s, w_gate, w_proj, w_fc1, w_fc2,
                                      p_wqkv, p_ws, p_wgate, p_wproj, p_wfc1, p_wfc2);

    // 1) LayerNorms of x and e -> split bf16
    ln2_split<<<2 * TOK, 128>>>(x, ln1_w, ln1_b, p_xn, e, ln2_w, ln2_b, p_en);

    // 2) qkv / s / gate projections (HMMA)
    gemm_mma<0><<<dim3(12, 64), 256, GEMM_SMEM>>>(p_xn, p_wqkv, nullptr, nullptr, p_qkv, TOK, 3 * CDIM, 3 * CDIM);
    gemm_mma<0><<<dim3(4,  64), 256, GEMM_SMEM>>>(p_en, p_ws,   nullptr, nullptr, p_s,   TOK, CDIM, 3 * CDIM);
    gemm_mma<0><<<dim3(4,  64), 256, GEMM_SMEM>>>(p_xn, p_wgate, nullptr, nullptr, p_gate, TOK, CDIM, 3 * CDIM);

    // 3) attention via HMMA (launch #6 -> ncu window)
    attn_mma<<<dim3(SEQ / 128, 4 * NHEAD), 256, ATT_SMEM>>>(p_qkv, p_s, p_gate, p_att);

    // 4) output projection + bias + residual(x) -> x1 (f32)
    gemm_mma<5><<<dim3(4, 64), 256, GEMM_SMEM>>>(p_att, p_wproj, b_proj, x, p_x1, TOK, CDIM, 3 * CDIM);

    // 5) MLP: LN3 -> fc1+bias+GELU (split out) -> fc2+bias+residual(x1) -> out
    ln_split<<<TOK, 128>>>(p_x1, ln3_w, ln3_b, p_xn3);
    gemm_mma<11><<<dim3(16, 64), 256, GEMM_SMEM>>>(p_xn3, p_wfc1, b_fc1, nullptr, p_h, TOK, DFF, 3 * CDIM);
    gemm_mma<5><<<dim3(4, 64), 256, GEMM_SMEM>>>(p_h, p_wfc2, b_fc2, p_x1, out, TOK, CDIM, 3 * DFF);
}

// round 17
// speedup vs baseline: 1.1393x; 1.1393x over previous
#include <cuda_runtime.h>
#include <cuda_bf16.h>
#include <math.h>
#include <stdint.h>

// Problem constants (fixed shapes from setup_inputs)
#define TOK   8192      // B*N = 4*2048 tokens
#define CDIM  512
#define DFF   2048
#define NHEAD 8
#define HDIM  64
#define SEQ   2048

// ------------------- scratch (device globals; no allocation) -------------------
__device__ float g_qkv [TOK * 3 * CDIM];
__device__ float g_s   [TOK * CDIM];
__device__ float g_gate[TOK * CDIM];
__device__ float g_x1  [TOK * CDIM];
// bf16 split activations: [M, 3K] layout = [hi | lo | hi]
__device__ __nv_bfloat16 b_xn  [TOK * 3 * CDIM];
__device__ __nv_bfloat16 b_en  [TOK * 3 * CDIM];
__device__ __nv_bfloat16 b_att [TOK * 3 * CDIM];
__device__ __nv_bfloat16 b_xn3 [TOK * 3 * CDIM];
__device__ __nv_bfloat16 b_h   [TOK * 3 * DFF];
// bf16 split weights: [N, 3K] layout = [Bh | Bh | Bl]  (K-major rows)
__device__ __nv_bfloat16 b_wqkv [3 * CDIM * 3 * CDIM];
__device__ __nv_bfloat16 b_ws   [CDIM * 3 * CDIM];
__device__ __nv_bfloat16 b_wgate[CDIM * 3 * CDIM];
__device__ __nv_bfloat16 b_wproj[CDIM * 3 * CDIM];
__device__ __nv_bfloat16 b_wfc1 [DFF * 3 * CDIM];
__device__ __nv_bfloat16 b_wfc2 [CDIM * 3 * DFF];
// attention prep: split (k+s) per token [r][h*128 + (hi64|lo64)], and split V^T per (b,h)
__device__ __nv_bfloat16 g_kps[TOK * NHEAD * 128];            // 16.8 MB
__device__ __nv_bfloat16 g_vt [4 * NHEAD * HDIM * 2 * SEQ];   // 33.6 MB

// ------------------- helpers -------------------
__device__ __forceinline__ uint32_t smem_u32(const void* p) {
    uint32_t a;
    asm("{ .reg .u64 t; cvta.to.shared.u64 t, %1; cvt.u32.u64 %0, t; }" : "=r"(a) : "l"(p));
    return a;
}
__device__ __forceinline__ void cp_async16(uint32_t dst, const void* src) {
    asm volatile("cp.async.cg.shared.global [%0], [%1], 16;" :: "r"(dst), "l"(src) : "memory");
}
__device__ __forceinline__ void cp_commit() {
    asm volatile("cp.async.commit_group;" ::: "memory");
}
template <int N>
__device__ __forceinline__ void cp_wait() {
    asm volatile("cp.async.wait_group %0;" :: "n"(N) : "memory");
}
__device__ __forceinline__ void mma16816(float* c, const uint32_t* a, const uint32_t* b) {
    asm volatile(
        "mma.sync.aligned.m16n8k16.row.col.f32.bf16.bf16.f32 "
        "{%0,%1,%2,%3}, {%4,%5,%6,%7}, {%8,%9}, {%0,%1,%2,%3};"
        : "+f"(c[0]), "+f"(c[1]), "+f"(c[2]), "+f"(c[3])
        : "r"(a[0]), "r"(a[1]), "r"(a[2]), "r"(a[3]), "r"(b[0]), "r"(b[1]));
}
__device__ __forceinline__ void ldsm_x4(uint32_t* r, uint32_t addr) {
    asm volatile("ldmatrix.sync.aligned.m8n8.x4.shared.b16 {%0,%1,%2,%3}, [%4];"
                 : "=r"(r[0]), "=r"(r[1]), "=r"(r[2]), "=r"(r[3]) : "r"(addr));
}

static __device__ __forceinline__ void store_split4(__nv_bfloat16* dst, size_t base, int seglen,
                                                    float a, float b, float c, float d) {
    __nv_bfloat16 h0 = __float2bfloat16(a), h1 = __float2bfloat16(b);
    __nv_bfloat16 h2 = __float2bfloat16(c), h3 = __float2bfloat16(d);
    *(__nv_bfloat162*)&dst[base]     = __halves2bfloat162(h0, h1);
    *(__nv_bfloat162*)&dst[base + 2] = __halves2bfloat162(h2, h3);
    *(__nv_bfloat162*)&dst[base + 2 * (size_t)seglen]     = __halves2bfloat162(h0, h1);
    *(__nv_bfloat162*)&dst[base + 2 * (size_t)seglen + 2] = __halves2bfloat162(h2, h3);
    float l0 = a - __bfloat162float(h0), l1 = b - __bfloat162float(h1);
    float l2 = c - __bfloat162float(h2), l3 = d - __bfloat162float(h3);
    *(__nv_bfloat162*)&dst[base + (size_t)seglen] =
        __halves2bfloat162(__float2bfloat16(l0), __float2bfloat16(l1));
    *(__nv_bfloat162*)&dst[base + (size_t)seglen + 2] =
        __halves2bfloat162(__float2bfloat16(l2), __float2bfloat16(l3));
}

static __device__ __forceinline__ void store_split2(__nv_bfloat16* dst, size_t base, int seglen,
                                                    float a, float b) {
    __nv_bfloat16 h0 = __float2bfloat16(a), h1 = __float2bfloat16(b);
    __nv_bfloat162 hp = __halves2bfloat162(h0, h1);
    *(__nv_bfloat162*)&dst[base] = hp;
    *(__nv_bfloat162*)&dst[base + 2 * (size_t)seglen] = hp;
    float l0 = a - __bfloat162float(h0), l1 = b - __bfloat162float(h1);
    *(__nv_bfloat162*)&dst[base + (size_t)seglen] =
        __halves2bfloat162(__float2bfloat16(l0), __float2bfloat16(l1));
}

static __device__ __forceinline__ void split_hl(float v, __nv_bfloat16& h, __nv_bfloat16& l) {
    h = __float2bfloat16(v);
    l = __float2bfloat16(v - __bfloat162float(h));
}

// ------------------- fused weight split: all 6 weights in one launch -------------------
__global__ void wsplit_all(
    const float* __restrict__ w0, const float* __restrict__ w1, const float* __restrict__ w2,
    const float* __restrict__ w3, const float* __restrict__ w4, const float* __restrict__ w5,
    __nv_bfloat16* __restrict__ o0, __nv_bfloat16* __restrict__ o1, __nv_bfloat16* __restrict__ o2,
    __nv_bfloat16* __restrict__ o3, __nv_bfloat16* __restrict__ o4, __nv_bfloat16* __restrict__ o5)
{
    int bid = blockIdx.x;
    const float* W; __nv_bfloat16* Wb; int K, N, t;
    if      (bid < 768)  { W = w0; Wb = o0; K = 512;  N = 1536; t = bid; }
    else if (bid < 1024) { W = w1; Wb = o1; K = 512;  N = 512;  t = bid - 768; }
    else if (bid < 1280) { W = w2; Wb = o2; K = 512;  N = 512;  t = bid - 1024; }
    else if (bid < 1536) { W = w3; Wb = o3; K = 512;  N = 512;  t = bid - 1280; }
    else if (bid < 2560) { W = w4; Wb = o4; K = 512;  N = 2048; t = bid - 1536; }
    else                 { W = w5; Wb = o5; K = 2048; N = 512;  t = bid - 2560; }
    int nx = N >> 5;
    int n0 = (t % nx) * 32, k0 = (t / nx) * 32;

    __shared__ float tile[32][33];
    int tx = threadIdx.x, ty = threadIdx.y;  // 32 x 8
    for (int i = ty; i < 32; i += 8) tile[i][tx] = W[(size_t)(k0 + i) * N + n0 + tx];
    __syncthreads();
    for (int i = ty; i < 32; i += 8) {
        int n = n0 + i, k = k0 + tx;
        float v = tile[tx][i];
        __nv_bfloat16 h = __float2bfloat16(v);
        float lo = v - __bfloat162float(h);
        size_t base = (size_t)n * 3 * K + k;
        Wb[base]         = h;
        Wb[base + K]     = h;
        Wb[base + 2 * K] = __float2bfloat16(lo);
    }
}

// ------------------- LayerNorm -> bf16 split triple -------------------
__global__ void ln2_split(const float* __restrict__ xa, const float* __restrict__ wa,
                          const float* __restrict__ ba, __nv_bfloat16* __restrict__ ya,
                          const float* __restrict__ xb, const float* __restrict__ wb,
                          const float* __restrict__ bb, __nv_bfloat16* __restrict__ yb)
{
    int row = blockIdx.x;
    const float *x = xa, *w = wa, *b = ba;
    __nv_bfloat16* y = ya;
    if (row >= TOK) { row -= TOK; x = xb; w = wb; b = bb; y = yb; }

    int tid = threadIdx.x;
    float4 v = ((const float4*)(x + (size_t)row * CDIM))[tid];
    float s  = v.x + v.y + v.z + v.w;
    float ss = v.x * v.x + v.y * v.y + v.z * v.z + v.w * v.w;
#pragma unroll
    for (int off = 16; off > 0; off >>= 1) {
        s  += __shfl_xor_sync(0xffffffffu, s,  off);
        ss += __shfl_xor_sync(0xffffffffu, ss, off);
    }
    __shared__ float rs[4], rss[4];
    int wid = tid >> 5;
    if ((tid & 31) == 0) { rs[wid] = s; rss[wid] = ss; }
    __syncthreads();
    s  = rs[0] + rs[1] + rs[2] + rs[3];
    ss = rss[0] + rss[1] + rss[2] + rss[3];
    float mean = s * (1.0f / CDIM);
    float var  = ss * (1.0f / CDIM) - mean * mean;
    float rstd = rsqrtf(var + 1e-5f);
    float4 w4 = ((const float4*)w)[tid];
    float4 b4 = ((const float4*)b)[tid];
    float o0 = (v.x - mean) * rstd * w4.x + b4.x;
    float o1 = (v.y - mean) * rstd * w4.y + b4.y;
    float o2 = (v.z - mean) * rstd * w4.z + b4.z;
    float o3 = (v.w - mean) * rstd * w4.w + b4.w;
    store_split4(y, (size_t)row * 3 * CDIM + tid * 4, CDIM, o0, o1, o2, o3);
}

__global__ void ln_split(const float* __restrict__ x, const float* __restrict__ w,
                         const float* __restrict__ b, __nv_bfloat16* __restrict__ y)
{
    int row = blockIdx.x;
    int tid = threadIdx.x;
    float4 v = ((const float4*)(x + (size_t)row * CDIM))[tid];
    float s  = v.x + v.y + v.z + v.w;
    float ss = v.x * v.x + v.y * v.y + v.z * v.z + v.w * v.w;
#pragma unroll
    for (int off = 16; off > 0; off >>= 1) {
        s  += __shfl_xor_sync(0xffffffffu, s,  off);
        ss += __shfl_xor_sync(0xffffffffu, ss, off);
    }
    __shared__ float rs[4], rss[4];
    int wid = tid >> 5;
    if ((tid & 31) == 0) { rs[wid] = s; rss[wid] = ss; }
    __syncthreads();
    s  = rs[0] + rs[1] + rs[2] + rs[3];
    ss = rss[0] + rss[1] + rss[2] + rss[3];
    float mean = s * (1.0f / CDIM);
    float var  = ss * (1.0f / CDIM) - mean * mean;
    float rstd = rsqrtf(var + 1e-5f);
    float4 w4 = ((const float4*)w)[tid];
    float4 b4 = ((const float4*)b)[tid];
    float o0 = (v.x - mean) * rstd * w4.x + b4.x;
    float o1 = (v.y - mean) * rstd * w4.y + b4.y;
    float o2 = (v.z - mean) * rstd * w4.z + b4.z;
    float o3 = (v.w - mean) * rstd * w4.w + b4.w;
    store_split4(y, (size_t)row * 3 * CDIM + tid * 4, CDIM, o0, o1, o2, o3);
}

// ------------------- attention prep: split (k+s) and transposed split V, once -------------------
// grid (SEQ/64, B*NHEAD), 256 threads.
// kps[r][h*128 + d]      = hi(k+s),  [.. + 64 + d] = lo(k+s)
// vt[bh][d][c]           = hi(V^T),  vt[bh][d][SEQ + c] = lo(V^T)
__global__ void kvprep(const float* __restrict__ qkv, const float* __restrict__ sbuf,
                       __nv_bfloat16* __restrict__ kps, __nv_bfloat16* __restrict__ vt)
{
    __shared__ float smv[64][65];
    const int bhy = blockIdx.y;
    const int bb  = bhy >> 3, hh = bhy & 7;
    const int c0  = blockIdx.x * 64;
    const int tid = threadIdx.x;
    const int koff = CDIM + hh * HDIM;
    const int voff = 2 * CDIM + hh * HDIM;
    const int soff = hh * HDIM;

    // K part: (k+s) split, row-major (no transpose)
    for (int i = tid; i < 64 * 16; i += 256) {
        int c  = i >> 4;
        int d4 = (i & 15) * 4;
        size_t row = (size_t)(bb * SEQ + c0 + c);
        float4 kv = *(const float4*)&qkv[row * (3 * CDIM) + koff + d4];
        float4 sv = *(const float4*)&sbuf[row * CDIM + soff + d4];
        kv.x += sv.x; kv.y += sv.y; kv.z += sv.z; kv.w += sv.w;
        __nv_bfloat16 h0, l0, h1, l1, h2, l2, h3, l3;
        split_hl(kv.x, h0, l0); split_hl(kv.y, h1, l1);
        split_hl(kv.z, h2, l2); split_hl(kv.w, h3, l3);
        size_t base = row * (NHEAD * 128) + hh * 128 + d4;
        *(__nv_bfloat162*)&kps[base]          = __halves2bfloat162(h0, h1);
        *(__nv_bfloat162*)&kps[base + 2]      = __halves2bfloat162(h2, h3);
        *(__nv_bfloat162*)&kps[base + 64]     = __halves2bfloat162(l0, l1);
        *(__nv_bfloat162*)&kps[base + 64 + 2] = __halves2bfloat162(l2, l3);
        // V into smem for transpose
        float4 vv = *(const float4*)&qkv[row * (3 * CDIM) + voff + d4];
        smv[c][d4 + 0] = vv.x; smv[c][d4 + 1] = vv.y;
        smv[c][d4 + 2] = vv.z; smv[c][d4 + 3] = vv.w;
    }
    __syncthreads();

    // V transpose + split
    for (int i = tid; i < 64 * 16; i += 256) {
        int d  = i >> 4;
        int c4 = (i & 15) * 4;
        float f0 = smv[c4 + 0][d], f1 = smv[c4 + 1][d];
        float f2 = smv[c4 + 2][d], f3 = smv[c4 + 3][d];
        __nv_bfloat16 h0, l0, h1, l1, h2, l2, h3, l3;
        split_hl(f0, h0, l0); split_hl(f1, h1, l1);
        split_hl(f2, h2, l2); split_hl(f3, h3, l3);
        size_t base = ((size_t)(bhy * HDIM + d)) * (2 * SEQ) + c0 + c4;
        *(__nv_bfloat162*)&vt[base]           = __halves2bfloat162(h0, h1);
        *(__nv_bfloat162*)&vt[base + 2]       = __halves2bfloat162(h2, h3);
        *(__nv_bfloat162*)&vt[base + SEQ]     = __halves2bfloat162(l0, l1);
        *(__nv_bfloat162*)&vt[base + SEQ + 2] = __halves2bfloat162(l2, l3);
    }
}

// ------------------- HMMA GEMM: C[M,N] = A'[M,K3] @ B'[N,K3]^T -------------------
__device__ __forceinline__ float gelu_erf(float v) {
    return 0.5f * v * (1.0f + erff(v * 0.70710678118654752f));
}

#define GPITCH_B 144                      // bytes per smem row (72 bf16)
#define GTILE_B  (128 * GPITCH_B)        // 18432 B per tile
#define GEMM_SMEM (4 * GTILE_B)          // A0,B0,A1,B1 = 73728 B

template <int MODE>
__global__ void __launch_bounds__(256, 2) gemm_mma(
    const __nv_bfloat16* __restrict__ A, const __nv_bfloat16* __restrict__ B,
    const float* __restrict__ bias, const float* __restrict__ res,
    void* __restrict__ Cout, int M, int N, int K3)
{
    extern __shared__ char sm[];
    const uint32_t smb = smem_u32(sm);
    const int tid  = threadIdx.x;
    const int lane = tid & 31;
    const int wid  = tid >> 5;
    const int wm   = wid >> 2;
    const int wn   = wid & 3;
    const int lr   = lane >> 2;
    const int lk2  = (lane & 3) * 2;

    const int m0 = blockIdx.y * 128, n0 = blockIdx.x * 128;
    const int NT = K3 >> 6;

    const int ldrow = tid >> 3;
    const int ldkc  = tid & 7;

    const int a_row  = wm * 64 + (lane & 15);
    const int a_boff = (lane >> 4) * 16;
    const int b_row  = wn * 32 + ((lane >> 4) & 1) * 8 + (lane & 7);
    const int b_boff = ((lane >> 3) & 1) * 16;

    float acc[4][4][4];
#pragma unroll
    for (int a = 0; a < 4; a++)
#pragma unroll
        for (int b = 0; b < 4; b++)
#pragma unroll
            for (int c = 0; c < 4; c++) acc[a][b][c] = 0.0f;

    auto issue = [&](int kt, int bsel) {
        uint32_t sa = smb + bsel * 2 * GTILE_B;
        uint32_t sb = sa + GTILE_B;
#pragma unroll
        for (int t = 0; t < 4; t++) {
            int row = ldrow + t * 32;
            uint32_t off = (uint32_t)(row * GPITCH_B + ldkc * 16);
            cp_async16(sa + off, A + (size_t)(m0 + row) * K3 + kt * 64 + ldkc * 8);
            cp_async16(sb + off, B + (size_t)(n0 + row) * K3 + kt * 64 + ldkc * 8);
        }
        cp_commit();
    };

    issue(0, 0);

    for (int kt = 0; kt < NT; kt++) {
        const int bsel = kt & 1;
        if (kt + 1 < NT) { issue(kt + 1, bsel ^ 1); cp_wait<1>(); }
        else             { cp_wait<0>(); }
        __syncthreads();

        const uint32_t bufA = smb + bsel * 2 * GTILE_B;
        const uint32_t bufB = bufA + GTILE_B;

#pragma unroll
        for (int s = 0; s < 4; s++) {
            uint32_t af[4][4];
#pragma unroll
            for (int mt = 0; mt < 4; mt++)
                ldsm_x4(af[mt], bufA + (a_row + mt * 16) * GPITCH_B + s * 32 + a_boff);
            uint32_t bfr[8];
#pragma unroll
            for (int p = 0; p < 2; p++)
                ldsm_x4(&bfr[p * 4], bufB + (b_row + p * 16) * GPITCH_B + s * 32 + b_boff);
#pragma unroll
            for (int mt = 0; mt < 4; mt++)
#pragma unroll
                for (int nt = 0; nt < 4; nt++)
                    mma16816(acc[mt][nt], af[mt], &bfr[nt * 2]);
        }
        __syncthreads();
    }

#pragma unroll
    for (int mt = 0; mt < 4; mt++) {
#pragma unroll
        for (int half = 0; half < 2; half++) {
            const int row = m0 + wm * 64 + mt * 16 + lr + half * 8;
#pragma unroll
            for (int nt = 0; nt < 4; nt++) {
                const int col = n0 + wn * 32 + nt * 8 + lk2;
                float v0 = acc[mt][nt][half * 2 + 0];
                float v1 = acc[mt][nt][half * 2 + 1];
                if (MODE & 1) {
                    float2 bb = *(const float2*)&bias[col];
                    v0 += bb.x; v1 += bb.y;
                }
                if (MODE & 2) { v0 = gelu_erf(v0); v1 = gelu_erf(v1); }
                if (MODE & 4) {
                    float2 rr = *(const float2*)&res[(size_t)row * N + col];
                    v0 += rr.x; v1 += rr.y;
                }
                if (MODE & 8) {
                    store_split2((__nv_bfloat16*)Cout, (size_t)row * 3 * N + col, N, v0, v1);
                } else {
                    float2 o = make_float2(v0, v1);
                    *(float2*)&((float*)Cout)[(size_t)row * N + col] = o;
                }
            }
        }
    }
}

// ------------------- Flash attention via HMMA, split-3, prep-fed tiles -------------------
#define APITCH 136
#define APITCH_B (APITCH * 2)
#define ATT_SMEM ((128 + 64 + 64 + 128) * APITCH * 2)   // 104448 B

__global__ void __launch_bounds__(256, 2) attn_mma(
    const float* __restrict__ qkv, const __nv_bfloat16* __restrict__ kps,
    const __nv_bfloat16* __restrict__ vt,
    const float* __restrict__ gate, __nv_bfloat16* __restrict__ out)
{
    extern __shared__ char smc[];
    __nv_bfloat16* qs = (__nv_bfloat16*)smc;        // [128][APITCH]  q*scale split
    __nv_bfloat16* ks = qs + 128 * APITCH;          // [64][APITCH]   (k+s) split
    __nv_bfloat16* vs = ks + 64 * APITCH;           // [64][APITCH]   V^T split
    __nv_bfloat16* ps = vs + 64 * APITCH;           // [128][APITCH]  P split

    const uint32_t qs_u = smem_u32(qs);
    const uint32_t ks_u = smem_u32(ks);
    const uint32_t vs_u = smem_u32(vs);
    const uint32_t ps_u = smem_u32(ps);

    const int tid  = threadIdx.x;
    const int lane = tid & 31;
    const int wid  = tid >> 5;          // 0..7
    const int wr0  = wid * 16;
    const int lr   = lane >> 2;
    const int lc2  = (lane & 3) * 2;

    const int a_row  = wr0 + (lane & 15);
    const int a_boff = (lane >> 4) * 16;
    const int b_row  = ((lane >> 4) & 1) * 8 + (lane & 7);
    const int b_boff = ((lane >> 3) & 1) * 16;

    const int bh = blockIdx.y;
    const int b  = bh >> 3, h = bh & 7;
    const int q0 = blockIdx.x * 128;
    const int mbase = b * SEQ;
    const int qoff = h * HDIM;
    const float scale = 0.125f;

    // load q tile: scale, split hi/lo (once per block)
    for (int i = tid; i < 128 * 16; i += 256) {
        int r  = i >> 4;
        int d4 = (i & 15) * 4;
        float4 v = *(const float4*)&qkv[(size_t)(mbase + q0 + r) * (3 * CDIM) + qoff + d4];
        v.x *= scale; v.y *= scale; v.z *= scale; v.w *= scale;
        __nv_bfloat16 h0, l0, h1, l1, h2, l2, h3, l3;
        split_hl(v.x, h0, l0); split_hl(v.y, h1, l1);
        split_hl(v.z, h2, l2); split_hl(v.w, h3, l3);
        __nv_bfloat16* row = qs + r * APITCH;
        *(__nv_bfloat162*)&row[d4]          = __halves2bfloat162(h0, h1);
        *(__nv_bfloat162*)&row[d4 + 2]      = __halves2bfloat162(h2, h3);
        *(__nv_bfloat162*)&row[64 + d4]     = __halves2bfloat162(l0, l1);
        *(__nv_bfloat162*)&row[64 + d4 + 2] = __halves2bfloat162(l2, l3);
    }

    float m_i[2] = {-1e30f, -1e30f};
    float l_i[2] = {0.0f, 0.0f};
    float oacc[8][4];
#pragma unroll
    for (int d = 0; d < 8; d++)
#pragma unroll
        for (int j = 0; j < 4; j++) oacc[d][j] = 0.0f;

    const __nv_bfloat16* vt_bh = vt + (size_t)bh * HDIM * 2 * SEQ;

    for (int kt = 0; kt < SEQ; kt += 64) {
        __syncthreads();   // previous iter's readers of ks/vs done
        // cp.async bf16 tiles straight from prep buffers (no conversion ALU)
        for (int i = tid; i < 64 * 16; i += 256) {
            int c = i >> 4, j = i & 15;
            cp_async16(ks_u + c * APITCH_B + j * 16,
                       kps + (size_t)(mbase + kt + c) * (NHEAD * 128) + h * 128 + j * 8);
        }
        for (int i = tid; i < 64 * 16; i += 256) {
            int d = i >> 4, j = i & 15;
            const __nv_bfloat16* src = vt_bh + (size_t)d * (2 * SEQ)
                                     + ((j < 8) ? (kt + j * 8) : (SEQ + kt + (j - 8) * 8));
            cp_async16(vs_u + d * APITCH_B + j * 16, src);
        }
        cp_commit();
        cp_wait<0>();
        __syncthreads();

        // scores S = q' @ (k+s)'^T  (split-3: hh, lh, hl)
        float sacc[8][4];
#pragma unroll
        for (int nt = 0; nt < 8; nt++)
#pragma unroll
            for (int j = 0; j < 4; j++) sacc[nt][j] = 0.0f;

#pragma unroll
        for (int s12 = 0; s12 < 12; s12++) {
            const int seg = s12 >> 2, ch = s12 & 3;
            const int qc = (seg == 1) ? 4 + ch : ch;
            const int kc = (seg == 2) ? 4 + ch : ch;
            uint32_t af[4];
            ldsm_x4(af, qs_u + a_row * APITCH_B + qc * 32 + a_boff);
            uint32_t bfr[16];
#pragma unroll
            for (int p = 0; p < 4; p++)
                ldsm_x4(&bfr[p * 4], ks_u + (b_row + p * 16) * APITCH_B + kc * 32 + b_boff);
#pragma unroll
            for (int nt = 0; nt < 8; nt++)
                mma16816(sacc[nt], af, &bfr[nt * 2]);
        }

        // online softmax
        float mx0 = -1e30f, mx1 = -1e30f;
#pragma unroll
        for (int nt = 0; nt < 8; nt++) {
            mx0 = fmaxf(mx0, fmaxf(sacc[nt][0], sacc[nt][1]));
            mx1 = fmaxf(mx1, fmaxf(sacc[nt][2], sacc[nt][3]));
        }
        mx0 = fmaxf(mx0, __shfl_xor_sync(0xffffffffu, mx0, 1));
        mx0 = fmaxf(mx0, __shfl_xor_sync(0xffffffffu, mx0, 2));
        mx1 = fmaxf(mx1, __shfl_xor_sync(0xffffffffu, mx1, 1));
        mx1 = fmaxf(mx1, __shfl_xor_sync(0xffffffffu, mx1, 2));
        const float mn0 = fmaxf(m_i[0], mx0);
        const float mn1 = fmaxf(m_i[1], mx1);
        const float corr0 = __expf(m_i[0] - mn0);
        const float corr1 = __expf(m_i[1] - mn1);
        float s0 = 0.0f, s1 = 0.0f;
#pragma unroll
        for (int nt = 0; nt < 8; nt++) {
            float p00 = __expf(sacc[nt][0] - mn0);
            float p01 = __expf(sacc[nt][1] - mn0);
            float p10 = __expf(sacc[nt][2] - mn1);
            float p11 = __expf(sacc[nt][3] - mn1);
            s0 += p00 + p01; s1 += p10 + p11;
            const int col = nt * 8 + lc2;
            __nv_bfloat16 h0, l0, h1, l1;
            split_hl(p00, h0, l0); split_hl(p01, h1, l1);
            __nv_bfloat16* r0 = ps + (wr0 + lr) * APITCH;
            *(__nv_bfloat162*)&r0[col]      = __halves2bfloat162(h0, h1);
            *(__nv_bfloat162*)&r0[64 + col] = __halves2bfloat162(l0, l1);
            split_hl(p10, h0, l0); split_hl(p11, h1, l1);
            __nv_bfloat16* r1 = ps + (wr0 + lr + 8) * APITCH;
            *(__nv_bfloat162*)&r1[col]      = __halves2bfloat162(h0, h1);
            *(__nv_bfloat162*)&r1[64 + col] = __halves2bfloat162(l0, l1);
        }
        s0 += __shfl_xor_sync(0xffffffffu, s0, 1);
        s0 += __shfl_xor_sync(0xffffffffu, s0, 2);
        s1 += __shfl_xor_sync(0xffffffffu, s1, 1);
        s1 += __shfl_xor_sync(0xffffffffu, s1, 2);
        l_i[0] = l_i[0] * corr0 + s0;
        l_i[1] = l_i[1] * corr1 + s1;
        m_i[0] = mn0; m_i[1] = mn1;
#pragma unroll
        for (int d = 0; d < 8; d++) {
            oacc[d][0] *= corr0; oacc[d][1] *= corr0;
            oacc[d][2] *= corr1; oacc[d][3] *= corr1;
        }
        __syncwarp();

        // PV: O += P' @ V'^T  (split-3)
#pragma unroll
        for (int s12 = 0; s12 < 12; s12++) {
            const int seg = s12 >> 2, ch = s12 & 3;
            const int pc = (seg == 1) ? 4 + ch : ch;
            const int vc = (seg == 2) ? 4 + ch : ch;
            uint32_t af[4];
            ldsm_x4(af, ps_u + a_row * APITCH_B + pc * 32 + a_boff);
            uint32_t bfr[16];
#pragma unroll
            for (int p = 0; p < 4; p++)
                ldsm_x4(&bfr[p * 4], vs_u + (b_row + p * 16) * APITCH_B + vc * 32 + b_boff);
#pragma unroll
            for (int dt = 0; dt < 8; dt++)
                mma16816(oacc[dt], af, &bfr[dt * 2]);
        }
    }

    const float inv0 = 1.0f / l_i[0];
    const float inv1 = 1.0f / l_i[1];
    const int r0 = mbase + q0 + wr0 + lr;
    const int r1 = r0 + 8;
#pragma unroll
    for (int dt = 0; dt < 8; dt++) {
        const int col = h * HDIM + dt * 8 + lc2;
        float2 g0 = *(const float2*)&gate[(size_t)r0 * CDIM + col];
        float2 g1 = *(const float2*)&gate[(size_t)r1 * CDIM + col];
        store_split2(out, (size_t)r0 * 3 * CDIM + col, CDIM,
                     oacc[dt][0] * inv0 * g0.x, oacc[dt][1] * inv0 * g0.y);
        store_split2(out, (size_t)r1 * 3 * CDIM + col, CDIM,
                     oacc[dt][2] * inv1 * g1.x, oacc[dt][3] * inv1 * g1.y);
    }
}

// ------------------- orchestration -------------------
extern "C" void kernel_launch(void* const* d_in, const int* in_sizes, int n_in,
                              void* d_out, int out_size)
{
    const float* x      = (const float*)d_in[0];
    const float* e      = (const float*)d_in[1];
    const float* w_qkv  = (const float*)d_in[2];
    const float* w_s    = (const float*)d_in[3];
    const float* w_gate = (const float*)d_in[4];
    const float* w_proj = (const float*)d_in[5];
    const float* b_proj = (const float*)d_in[6];
    const float* ln1_w  = (const float*)d_in[7];
    const float* ln1_b  = (const float*)d_in[8];
    const float* ln2_w  = (const float*)d_in[9];
    const float* ln2_b  = (const float*)d_in[10];
    const float* ln3_w  = (const float*)d_in[11];
    const float* ln3_b  = (const float*)d_in[12];
    const float* w_fc1  = (const float*)d_in[13];
    const float* b_fc1  = (const float*)d_in[14];
    const float* w_fc2  = (const float*)d_in[15];
    const float* b_fc2  = (const float*)d_in[16];
    float* out = (float*)d_out;

    float *p_qkv, *p_s, *p_gate, *p_x1;
    __nv_bfloat16 *p_xn, *p_en, *p_att, *p_xn3, *p_h, *p_kps, *p_vt;
    __nv_bfloat16 *p_wqkv, *p_ws, *p_wgate, *p_wproj, *p_wfc1, *p_wfc2;
    cudaGetSymbolAddress((void**)&p_qkv,  g_qkv);
    cudaGetSymbolAddress((void**)&p_s,    g_s);
    cudaGetSymbolAddress((void**)&p_gate, g_gate);
    cudaGetSymbolAddress((void**)&p_x1,   g_x1);
    cudaGetSymbolAddress((void**)&p_xn,   b_xn);
    cudaGetSymbolAddress((void**)&p_en,   b_en);
    cudaGetSymbolAddress((void**)&p_att,  b_att);
    cudaGetSymbolAddress((void**)&p_xn3,  b_xn3);
    cudaGetSymbolAddress((void**)&p_h,    b_h);
    cudaGetSymbolAddress((void**)&p_kps,  g_kps);
    cudaGetSymbolAddress((void**)&p_vt,   g_vt);
    cudaGetSymbolAddress((void**)&p_wqkv, b_wqkv);
    cudaGetSymbolAddress((void**)&p_ws,   b_ws);
    cudaGetSymbolAddress((void**)&p_wgate, b_wgate);
    cudaGetSymbolAddress((void**)&p_wproj, b_wproj);
    cudaGetSymbolAddress((void**)&p_wfc1, b_wfc1);
    cudaGetSymbolAddress((void**)&p_wfc2, b_wfc2);

    cudaFuncSetAttribute(attn_mma, cudaFuncAttributeMaxDynamicSharedMemorySize, ATT_SMEM);
    cudaFuncSetAttribute(gemm_mma<0>,  cudaFuncAttributeMaxDynamicSharedMemorySize, GEMM_SMEM);
    cudaFuncSetAttribute(gemm_mma<5>,  cudaFuncAttributeMaxDynamicSharedMemorySize, GEMM_SMEM);
    cudaFuncSetAttribute(gemm_mma<11>, cudaFuncAttributeMaxDynamicSharedMemorySize, GEMM_SMEM);

    // 0) split all weights -> bf16 [N,3K] (one launch)
    wsplit_all<<<3584, dim3(32, 8)>>>(w_qkv, w_s, w_gate, w_proj, w_fc1, w_fc2,
                                      p_wqkv, p_ws, p_wgate, p_wproj, p_wfc1, p_wfc2);

    // 1) LayerNorms of x and e -> split bf16
    ln2_split<<<2 * TOK, 128>>>(x, ln1_w, ln1_b, p_xn, e, ln2_w, ln2_b, p_en);

    // 2) qkv / s / gate projections (HMMA)
    gemm_mma<0><<<dim3(12, 64), 256, GEMM_SMEM>>>(p_xn, p_wqkv, nullptr, nullptr, p_qkv, TOK, 3 * CDIM, 3 * CDIM);
    gemm_mma<0><<<dim3(4,  64), 256, GEMM_SMEM>>>(p_en, p_ws,   nullptr, nullptr, p_s,   TOK, CDIM, 3 * CDIM);
    gemm_mma<0><<<dim3(4,  64), 256, GEMM_SMEM>>>(p_xn, p_wgate, nullptr, nullptr, p_gate, TOK, CDIM, 3 * CDIM);

    // 3) prep split (k+s) and V^T once, then attention
    kvprep<<<dim3(SEQ / 64, 4 * NHEAD), 256>>>(p_qkv, p_s, p_kps, p_vt);
    attn_mma<<<dim3(SEQ / 128, 4 * NHEAD), 256, ATT_SMEM>>>(p_qkv, p_kps, p_vt, p_gate, p_att);

    // 4) output projection + bias + residual(x) -> x1 (f32)
    gemm_mma<5><<<dim3(4, 64), 256, GEMM_SMEM>>>(p_att, p_wproj, b_proj, x, p_x1, TOK, CDIM, 3 * CDIM);

    // 5) MLP: LN3 -> fc1+bias+GELU (split out) -> fc2+bias+residual(x1) -> out
    ln_split<<<TOK, 128>>>(p_x1, ln3_w, ln3_b, p_xn3);
    gemm_mma<11><<<dim3(16, 64), 256, GEMM_SMEM>>>(p_xn3, p_wfc1, b_fc1, nullptr, p_h, TOK, DFF, 3 * CDIM);
    gemm_mma<5><<<dim3(4, 64), 256, GEMM_SMEM>>>(p_h, p_wfc2, b_fc2, p_x1, out, TOK, CDIM, 3 * DFF);
}